// round 14
// baseline (speedup 1.0000x reference)
#include <cuda_runtime.h>
#include <cuda_bf16.h>
#include <math.h>

#define BB 8
#define CC 128
#define NN 9216
#define EE 16

// ---------------- scratch ----------------
__device__ float g_node [BB*NN*CC];
__device__ float g_part [BB*72*EE*CC];
__device__ float g_hyper [BB*EE*CC];
__device__ float g_hyperF[BB*EE*CC];
__device__ float g_V [BB*EE*CC];
__device__ float g_Kp[BB*EE*CC];
__device__ float g_kb[BB*EE];
__device__ float g_Hw[BB*EE*CC];
__device__ float g_Vw[BB*EE*CC];
__device__ float g_GH[BB*EE*EE];
__device__ float g_GV[BB*EE*EE];
__device__ float g_hs[BB*EE];
__device__ float g_vs[BB*EE];
__device__ float g_u[CC];
__device__ float g_t[CC];
__device__ uint2 g_whl[CC*64];   // nproj_w bf16 (hi,lo) interleaved, pairs along k

__device__ __forceinline__ float gelu_exact(float x){
    return 0.5f*x*(1.0f + erff(x*0.70710678118654752f));
}

__device__ __forceinline__ void mma_bf16(float* d, const unsigned int* a,
                                         unsigned int b0, unsigned int b1){
    asm volatile(
      "mma.sync.aligned.m16n8k16.row.col.f32.bf16.bf16.f32 "
      "{%0,%1,%2,%3}, {%4,%5,%6,%7}, {%8,%9}, {%0,%1,%2,%3};\n"
      : "+f"(d[0]), "+f"(d[1]), "+f"(d[2]), "+f"(d[3])
      : "r"(a[0]), "r"(a[1]), "r"(a[2]), "r"(a[3]), "r"(b0), "r"(b1));
}

__device__ __forceinline__ void bf16_split2(float2 v, unsigned int& hi, unsigned int& lo){
    __nv_bfloat162 h = __float22bfloat162_rn(v);
    float2 back = __bfloat1622float2(h);
    __nv_bfloat162 l = __float22bfloat162_rn(make_float2(v.x - back.x, v.y - back.y));
    hi = *(unsigned int*)&h;
    lo = *(unsigned int*)&l;
}

// ============ kernel 1: transpose + LayerNorm(node) + agg partials ============
__global__ void __launch_bounds__(512)
k_node_ln(const float* __restrict__ fm,
          const float* __restrict__ gam,
          const float* __restrict__ bet,
          const float* __restrict__ sc)
{
    extern __shared__ float sm[];
    float* tile   = sm;              // 128*129
    float* s_sc   = tile + 16512;    // 2048
    float* s_part = s_sc + 2048;     // 8192
    float* s_mean = s_part + 8192;   // 128
    float* s_rstd = s_mean + 128;    // 128
    int b  = blockIdx.x / 72;
    int n0 = (blockIdx.x % 72) * 128;
    int tid = threadIdx.x;

    for (int i = tid; i < 16384; i += 512){
        int c = i >> 7, n = i & 127;
        tile[n*129 + c] = fm[(size_t)(b*CC + c)*NN + n0 + n];
    }
    for (int i = tid; i < 2048; i += 512)
        s_sc[i] = sc[(size_t)(b*NN + n0)*EE + i];
    __syncthreads();

    int w = tid >> 5, lane = tid & 31;
    for (int n = w*8; n < w*8 + 8; n++){
        float v0 = tile[n*129+lane],    v1 = tile[n*129+lane+32];
        float v2 = tile[n*129+lane+64], v3 = tile[n*129+lane+96];
        float s = v0+v1+v2+v3;
        for (int o=16;o;o>>=1) s += __shfl_xor_sync(0xffffffffu, s, o);
        float m = s * (1.0f/128.0f);
        float d0=v0-m, d1=v1-m, d2=v2-m, d3=v3-m;
        float q = d0*d0+d1*d1+d2*d2+d3*d3;
        for (int o=16;o;o>>=1) q += __shfl_xor_sync(0xffffffffu, q, o);
        if (lane == 0){ s_mean[n]=m; s_rstd[n]=rsqrtf(q*(1.0f/128.0f)+1e-5f); }
    }
    __syncthreads();

    int c = tid & 127, q = tid >> 7;
    float gg = gam[c], bb = bet[c];
    float acc[16];
    #pragma unroll
    for (int e=0;e<16;e++) acc[e]=0.f;
    for (int n = q*32; n < q*32 + 32; n++){
        float v = (tile[n*129+c]-s_mean[n])*s_rstd[n]*gg + bb;
        g_node[(size_t)(b*NN + n0 + n)*CC + c] = v;
        const float4* scr = (const float4*)(s_sc + n*16);
        float4 a0 = scr[0], a1 = scr[1], a2 = scr[2], a3 = scr[3];
        acc[0]  += a0.x*v; acc[1]  += a0.y*v; acc[2]  += a0.z*v; acc[3]  += a0.w*v;
        acc[4]  += a1.x*v; acc[5]  += a1.y*v; acc[6]  += a1.z*v; acc[7]  += a1.w*v;
        acc[8]  += a2.x*v; acc[9]  += a2.y*v; acc[10] += a2.z*v; acc[11] += a2.w*v;
        acc[12] += a3.x*v; acc[13] += a3.y*v; acc[14] += a3.z*v; acc[15] += a3.w*v;
    }
    #pragma unroll
    for (int e=0;e<16;e++) s_part[q*2048 + e*128 + c] = acc[e];
    __syncthreads();

    for (int i = tid; i < 2048; i += 512){
        float s = s_part[i] + s_part[2048+i] + s_part[4096+i] + s_part[6144+i];
        g_part[(size_t)(b*72 + (blockIdx.x%72))*2048 + i] = s;
    }
}

// ============ kernel 2: reduce + batch-independent precomputes ============
__global__ void __launch_bounds__(512)
k_reduce_prep(const float* __restrict__ gate_w, const float* __restrict__ gate_b,
              const float* __restrict__ nf_g, const float* __restrict__ nf_b,
              const float* __restrict__ nproj_w)
{
    int blk = blockIdx.x, tid = threadIdx.x;
    if (blk < 32){
        int i = blk*512 + tid;
        int b = i >> 11, rem = i & 2047;
        float s = 0.f;
        #pragma unroll 4
        for (int j = 0; j < 72; j++) s += g_part[(size_t)(b*72 + j)*2048 + rem];
        g_hyper[b*2048 + rem] = s;
    } else if (blk < 36){
        int j = (blk-32)*32 + (tid >> 4);
        int l = tid & 15;
        float t = 0.f, u = 0.f;
        #pragma unroll
        for (int k = 0; k < 16; k++){
            int c = l + k*16;
            float w = gate_w[j*256 + c];
            t += nf_b[c]*w; u += nf_g[c]*w;
        }
        #pragma unroll
        for (int o = 8; o; o >>= 1){
            t += __shfl_xor_sync(0xffffffffu, t, o);
            u += __shfl_xor_sync(0xffffffffu, u, o);
        }
        if (l == 0){ g_t[j] = t + gate_b[j]; g_u[j] = u; }
    } else {
        int i = (blk-36)*512 + tid;
        unsigned int hi, lo;
        bf16_split2(((const float2*)nproj_w)[i], hi, lo);
        g_whl[i] = make_uint2(hi, lo);
    }
}

// ============ kernel 3: hyperedge transformer + fused per-batch precomputes ============
template<int CIN, int COUT, int ACT, int BS>
__device__ __forceinline__ void gemmF(const float* __restrict__ W,
                                      const float* __restrict__ bias,
                                      const float* in, int inPitch,
                                      float* out, int outPitch, float* sw)
{
    const int pitch = CIN + 4;
    const int cin4  = CIN >> 2;
    const float4* W4 = (const float4*)W;
    for (int i = threadIdx.x; i < (COUT*CIN)>>2; i += BS){
        int r = i / cin4, c4 = i - r*cin4;
        ((float4*)(sw + r*pitch))[c4] = W4[i];
    }
    __syncthreads();
    const int logC  = (COUT == 256) ? 8 : 7;
    const int estep = BS >> logC;
    const int nE    = 16 / estep;
    int j  = threadIdx.x & (COUT-1);
    int e0 = threadIdx.x >> logC;
    const float4* wr = (const float4*)(sw + j*pitch);
    float acc[nE];
    const float4* ar[nE];
    #pragma unroll
    for (int r=0;r<nE;r++){ acc[r]=0.f; ar[r]=(const float4*)(in + (e0 + r*estep)*inPitch); }
    for (int kk = 0; kk < cin4; kk++){
        float4 wv = wr[kk];
        #pragma unroll
        for (int r=0;r<nE;r++){
            float4 av = ar[r][kk];
            acc[r] += av.x*wv.x + av.y*wv.y + av.z*wv.z + av.w*wv.w;
        }
    }
    float bj = bias[j];
    #pragma unroll
    for (int r=0;r<nE;r++){
        float v = acc[r] + bj;
        if (ACT) v = gelu_exact(v);
        out[(e0 + r*estep)*outPitch + j] = v;
    }
    __syncthreads();
}

__device__ __forceinline__ void ln16_128(const float* a, const float* r, int pitch,
                                         const float* __restrict__ g,
                                         const float* __restrict__ b,
                                         float* out, int outPitch)
{
    int w = threadIdx.x >> 5, lane = threadIdx.x & 31;
    if (w < 16){
        float v[4]; float s = 0.f;
        #pragma unroll
        for (int i=0;i<4;i++){
            float x = a[w*pitch + lane + 32*i];
            if (r) x += r[w*pitch + lane + 32*i];
            v[i] = x; s += x;
        }
        for (int o=16;o;o>>=1) s += __shfl_xor_sync(0xffffffffu, s, o);
        float m = s*(1.f/128.f), q = 0.f;
        #pragma unroll
        for (int i=0;i<4;i++){ float d=v[i]-m; q += d*d; }
        for (int o=16;o;o>>=1) q += __shfl_xor_sync(0xffffffffu, q, o);
        float rs = rsqrtf(q*(1.f/128.f)+1e-5f);
        #pragma unroll
        for (int i=0;i<4;i++)
            out[w*outPitch + lane + 32*i] = (v[i]-m)*rs*g[lane+32*i] + b[lane+32*i];
    }
    __syncthreads();
}

__global__ void __launch_bounds__(1024)
k_hyper(const float* __restrict__ mha_w_in, const float* __restrict__ mha_b_in,
        const float* __restrict__ mha_w_out, const float* __restrict__ mha_b_out,
        const float* __restrict__ ffn_w1, const float* __restrict__ ffn_b1,
        const float* __restrict__ ffn_w2, const float* __restrict__ ffn_b2,
        const float* __restrict__ tnorm_g, const float* __restrict__ tnorm_b,
        const float* __restrict__ nh_g, const float* __restrict__ nh_b,
        const float* __restrict__ hp_w, const float* __restrict__ hp_b,
        const float* __restrict__ kv_w, const float* __restrict__ kv_b,
        const float* __restrict__ q_w, const float* __restrict__ q_b,
        const float* __restrict__ gate_w, const float* __restrict__ nf_g)
{
    extern __shared__ float sm[];
    float* s0   = sm;            // 16*132
    float* s1   = s0 + 2112;
    float* s2   = s1 + 2112;
    float* s3   = s2 + 2112;
    float* sh   = s3 + 2112;     // 16*264
    float* satt = sh + 4224;     // 1024
    float* sw   = satt + 1024;   // 33792
    int b = blockIdx.x, tid = threadIdx.x;

    for (int i = tid; i < 2048; i += 1024)
        s0[(i>>7)*132 + (i&127)] = g_hyper[b*2048 + i];
    __syncthreads();

    gemmF<128,128,0,1024>(mha_w_in,           mha_b_in,     s0,132, s1,132, sw);
    gemmF<128,128,0,1024>(mha_w_in + 128*128, mha_b_in+128, s0,132, s2,132, sw);
    gemmF<128,128,0,1024>(mha_w_in + 256*128, mha_b_in+256, s0,132, s3,132, sw);

    {
        int p = tid;
        if (p < 1024){
            int h = p>>8, e1 = (p>>4)&15, e2 = p&15;
            const float* qr = s1 + e1*132 + h*32;
            const float* kr = s2 + e2*132 + h*32;
            float acc = 0.f;
            #pragma unroll
            for (int d=0; d<32; d++) acc += qr[d]*kr[d];
            satt[p] = acc * 0.17677669529663687f;
        }
    }
    __syncthreads();
    if (tid < 64){
        float* row = satt + tid*16;
        float mx = row[0];
        #pragma unroll
        for (int e=1;e<16;e++) mx = fmaxf(mx, row[e]);
        float s = 0.f;
        #pragma unroll
        for (int e=0;e<16;e++){ float v = expf(row[e]-mx); row[e]=v; s+=v; }
        float inv = 1.f/s;
        #pragma unroll
        for (int e=0;e<16;e++) row[e] *= inv;
    }
    __syncthreads();
    for (int p = tid; p < 2048; p += 1024){
        int e = p>>7, c = p&127, h = c>>5;
        float acc = 0.f;
        #pragma unroll
        for (int e2=0;e2<16;e2++) acc += satt[(h*16+e)*16 + e2] * s3[e2*132 + c];
        s1[e*132 + c] = acc;
    }
    __syncthreads();
    gemmF<128,128,0,1024>(mha_w_out, mha_b_out, s1,132, s2,132, sw);
    ln16_128(s0, s2, 132, tnorm_g, tnorm_b, s3, 132);
    gemmF<128,256,1,1024>(ffn_w1, ffn_b1, s3,132, sh,264, sw);
    gemmF<256,128,0,1024>(ffn_w2, ffn_b2, sh,264, s1,132, sw);
    ln16_128(s3, s1, 132, tnorm_g, tnorm_b, s2, 132);
    ln16_128(s2, (const float*)0, 132, nh_g, nh_b, s3, 132);
    gemmF<128,128,1,1024>(hp_w, hp_b, s3,132, s0,132, sw);               // H -> s0
    gemmF<128,128,0,1024>(kv_w,           kv_b,     s0,132, s1,132, sw); // K -> s1
    gemmF<128,128,0,1024>(kv_w + 128*128, kv_b+128, s0,132, s2,132, sw); // V -> s2

    // store H, V for k_node (K is consumed here, no global round-trip)
    for (int i = tid; i < 2048; i += 1024){
        int e = i>>7, c = i&127, o = b*2048 + i;
        g_hyperF[o] = s0[e*132+c];
        g_V[o]      = s2[e*132+c];
    }

    // ---- fused precompute tail (was k_prep) ----
    // Kp[e,k] = scl * sum_j K[e,j] q_w[j,k];  kb[e] = scl * q_b . K[e]
    for (int i = tid; i < 16384; i += 1024){
        int j = i >> 7, k = i & 127;
        sw[k*132 + j] = q_w[i];            // transposed stage
    }
    __syncthreads();
    {
        const float scl = 0.08838834764831845f;
        for (int o = tid; o < 2048; o += 1024){
            int e = o>>7, k = o&127;
            const float4* ar = (const float4*)(s1 + e*132);
            const float4* wr = (const float4*)(sw + k*132);
            float acc = 0.f;
            #pragma unroll 8
            for (int kk = 0; kk < 32; kk++){
                float4 a = ar[kk], w = wr[kk];
                acc += a.x*w.x + a.y*w.y + a.z*w.z + a.w*w.w;
            }
            g_Kp[b*2048 + o] = acc * scl;
        }
        if (tid < 16){
            float acc = 0.f;
            for (int c = 0; c < 128; c++) acc += q_b[c]*s1[tid*132+c];
            g_kb[b*16 + tid] = acc * scl;
        }
    }
    __syncthreads();

    // Hw[e,j] = sum_c H[e,c] * gate_w[j,c]*nf_g[c]
    for (int i = tid; i < 16384; i += 1024){
        int j = i >> 7, c = i & 127;
        sw[j*132 + c] = gate_w[j*256 + c] * nf_g[c];
    }
    __syncthreads();
    for (int p = tid; p < 2048; p += 1024){
        int e = p >> 7, j = p & 127;
        const float4* ar = (const float4*)(s0 + e*132);
        const float4* wr = (const float4*)(sw + j*132);
        float acc = 0.f;
        #pragma unroll 8
        for (int kk = 0; kk < 32; kk++){
            float4 a = ar[kk], w = wr[kk];
            acc += a.x*w.x + a.y*w.y + a.z*w.z + a.w*w.w;
        }
        g_Hw[b*2048 + p] = acc;
    }
    __syncthreads();

    // Vw[e,j] = sum_c V[e,c] * gate_w[j,128+c]*nf_g[128+c]
    for (int i = tid; i < 16384; i += 1024){
        int j = i >> 7, c = i & 127;
        sw[j*132 + c] = gate_w[j*256 + 128 + c] * nf_g[128 + c];
    }
    __syncthreads();
    for (int p = tid; p < 2048; p += 1024){
        int e = p >> 7, j = p & 127;
        const float4* ar = (const float4*)(s2 + e*132);
        const float4* wr = (const float4*)(sw + j*132);
        float acc = 0.f;
        #pragma unroll 8
        for (int kk = 0; kk < 32; kk++){
            float4 a = ar[kk], w = wr[kk];
            acc += a.x*w.x + a.y*w.y + a.z*w.z + a.w*w.w;
        }
        g_Vw[b*2048 + p] = acc;
    }

    // Gram matrices + row sums (read-only on s0/s2; no extra barrier needed)
    if (tid < 512){
        const float* A = (tid < 256) ? s0 : s2;
        int qq = tid & 255;
        int e = qq >> 4, f = qq & 15;
        const float4* r1 = (const float4*)(A + e*132);
        const float4* r2 = (const float4*)(A + f*132);
        float acc = 0.f;
        #pragma unroll 8
        for (int kk = 0; kk < 32; kk++){
            float4 a = r1[kk], c = r2[kk];
            acc += a.x*c.x + a.y*c.y + a.z*c.z + a.w*c.w;
        }
        if (tid < 256) g_GH[b*256+qq] = acc; else g_GV[b*256+qq] = acc;
    } else if (tid < 544){
        int e = (tid - 512) & 15;
        const float* A = (tid < 528) ? s0 : s2;
        float s = 0.f;
        for (int c = 0; c < 128; c++) s += A[e*132+c];
        if (tid < 528) g_hs[b*16+e] = s; else g_vs[b*16+e] = s;
    }
}

// ============ kernel 4: FUSED per-node pipeline ============
// grid 1152 (8*144), block 256, 64 nodes/block, ~90KB smem -> 2 blocks/SM
__global__ void __launch_bounds__(256)
k_node(const float* __restrict__ sc,
       const float* __restrict__ gl_g, const float* __restrict__ gl_b,
       const float* __restrict__ nproj_b,
       float* __restrict__ out)
{
    extern __shared__ float sm[];
    float* s_node = sm;              // 8448 (64*132)
    float* s_Kp   = s_node + 8448;   // 2112
    float* s_H    = s_Kp   + 2112;
    float* s_V    = s_H    + 2112;
    float* s_Hw   = s_V    + 2112;
    float* s_Vw   = s_Hw   + 2112;
    float* s_att  = s_Vw   + 2112;   // 1024 (64*16)
    float* s_sc   = s_att  + 1024;   // 1024
    float* s_GH   = s_sc   + 1024;   // 256
    float* s_GV   = s_GH   + 256;
    float* s_u    = s_GV   + 256;    // 128
    float* s_t    = s_u    + 128;
    float* s_m    = s_t    + 128;    // 64
    float* s_rs   = s_m    + 64;
    float* s_sp   = s_rs   + 64;     // 256 (64*4)
    float* s_sq   = s_sp   + 256;    // 256
    float* s_hs   = s_sq   + 256;    // 16
    float* s_vs   = s_hs   + 16;
    float* s_kb   = s_vs   + 16;

    int b  = blockIdx.x / 144;
    int n0 = (blockIdx.x % 144) * 64;
    int tid = threadIdx.x;

    // ---- stage ----
    for (int i4 = tid; i4 < 2048; i4 += 256){
        int n = i4 >> 5, c4 = i4 & 31;
        ((float4*)(s_node + n*132))[c4] =
            ((const float4*)(g_node + (size_t)(b*NN + n0 + n)*CC))[c4];
    }
    for (int i4 = tid; i4 < 512; i4 += 256){
        int e = i4 >> 5, c4 = i4 & 31;
        ((float4*)(s_Kp + e*132))[c4] = ((const float4*)(g_Kp    + b*2048))[i4];
        ((float4*)(s_H  + e*132))[c4] = ((const float4*)(g_hyperF+ b*2048))[i4];
        ((float4*)(s_V  + e*132))[c4] = ((const float4*)(g_V     + b*2048))[i4];
        ((float4*)(s_Hw + e*132))[c4] = ((const float4*)(g_Hw    + b*2048))[i4];
        ((float4*)(s_Vw + e*132))[c4] = ((const float4*)(g_Vw    + b*2048))[i4];
    }
    {
        int i4 = tid;
        if (i4 < 256) ((float4*)s_sc)[i4] = ((const float4*)(sc + (size_t)(b*NN + n0)*16))[i4];
        if (i4 < 64){
            ((float4*)s_GH)[i4] = ((const float4*)(g_GH + b*256))[i4];
            ((float4*)s_GV)[i4] = ((const float4*)(g_GV + b*256))[i4];
        }
        if (i4 < 32){
            ((float4*)s_u)[i4] = ((const float4*)g_u)[i4];
            ((float4*)s_t)[i4] = ((const float4*)g_t)[i4];
        }
        if (i4 < 16){ s_hs[i4]=g_hs[b*16+i4]; s_vs[i4]=g_vs[b*16+i4]; s_kb[i4]=g_kb[b*16+i4]; }
    }
    __syncthreads();

    // ---- logits ----
    {
        int n = tid >> 2, q = tid & 3;
        const float4* nr = (const float4*)(s_node + n*132);
        float acc[4] = {0.f,0.f,0.f,0.f};
        const float4* kp0 = (const float4*)(s_Kp + (q*4+0)*132);
        const float4* kp1 = (const float4*)(s_Kp + (q*4+1)*132);
        const float4* kp2 = (const float4*)(s_Kp + (q*4+2)*132);
        const float4* kp3 = (const float4*)(s_Kp + (q*4+3)*132);
        #pragma unroll 8
        for (int kk = 0; kk < 32; kk++){
            float4 a = nr[kk];
            float4 k0 = kp0[kk], k1 = kp1[kk], k2 = kp2[kk], k3 = kp3[kk];
            acc[0] += a.x*k0.x + a.y*k0.y + a.z*k0.z + a.w*k0.w;
            acc[1] += a.x*k1.x + a.y*k1.y + a.z*k1.z + a.w*k1.w;
            acc[2] += a.x*k2.x + a.y*k2.y + a.z*k2.z + a.w*k2.w;
            acc[3] += a.x*k3.x + a.y*k3.y + a.z*k3.z + a.w*k3.w;
        }
        #pragma unroll
        for (int i=0;i<4;i++) s_att[n*16 + q*4 + i] = acc[i] + s_kb[q*4+i];
    }
    __syncthreads();

    // ---- softmax + LN256 stats (tid<64) ----
    if (tid < 64){
        int n = tid;
        float scv[16], atv[16];
        float* row = s_att + n*16;
        float mx = row[0];
        #pragma unroll
        for (int e=1;e<16;e++) mx = fmaxf(mx, row[e]);
        float s = 0.f;
        #pragma unroll
        for (int e=0;e<16;e++){ float v = expf(row[e]-mx); atv[e]=v; s+=v; }
        float inv = 1.f/s;
        #pragma unroll
        for (int e=0;e<16;e++){ atv[e] *= inv; row[e] = atv[e]; scv[e] = s_sc[n*16+e]; }
        float mean = 0.f;
        #pragma unroll
        for (int e=0;e<16;e++) mean += scv[e]*s_hs[e] + atv[e]*s_vs[e];
        mean *= (1.f/256.f);
        float ssq = 0.f;
        #pragma unroll
        for (int e=0;e<16;e++){
            float t1 = 0.f, t2 = 0.f;
            #pragma unroll
            for (int f=0;f<16;f++){
                t1 += scv[f]*s_GH[e*16+f];
                t2 += atv[f]*s_GV[e*16+f];
            }
            ssq += scv[e]*t1 + atv[e]*t2;
        }
        float var = ssq*(1.f/256.f) - mean*mean;
        s_m[n] = mean;
        s_rs[n] = rsqrtf(var + 1e-5f);
    }
    __syncthreads();

    // ---- gate rank-16 in registers + LN stat partials ----
    float gp[4][8];
    {
        int j = tid & 127, g = tid >> 7, sub = (tid >> 5) & 3;
        float uj = s_u[j], tj = s_t[j];
        #pragma unroll
        for (int blk = 0; blk < 4; blk++){
            int nb = g*32 + blk*8;
            float acc[8] = {0,0,0,0,0,0,0,0};
            #pragma unroll
            for (int kk = 0; kk < 4; kk++){
                float b0 = s_Hw[(kk*4+0)*132 + j];
                float b1 = s_Hw[(kk*4+1)*132 + j];
                float b2 = s_Hw[(kk*4+2)*132 + j];
                float b3 = s_Hw[(kk*4+3)*132 + j];
                #pragma unroll
                for (int i=0;i<8;i++){
                    float4 a = ((const float4*)(s_sc + (nb+i)*16))[kk];
                    acc[i] += a.x*b0 + a.y*b1 + a.z*b2 + a.w*b3;
                }
            }
            #pragma unroll
            for (int kk = 0; kk < 4; kk++){
                float b0 = s_Vw[(kk*4+0)*132 + j];
                float b1 = s_Vw[(kk*4+1)*132 + j];
                float b2 = s_Vw[(kk*4+2)*132 + j];
                float b3 = s_Vw[(kk*4+3)*132 + j];
                #pragma unroll
                for (int i=0;i<8;i++){
                    float4 a = ((const float4*)(s_att + (nb+i)*16))[kk];
                    acc[i] += a.x*b0 + a.y*b1 + a.z*b2 + a.w*b3;
                }
            }
            #pragma unroll
            for (int i=0;i<8;i++){
                int n = nb + i;
                float v = s_rs[n]*(acc[i] - s_m[n]*uj) + tj;
                gp[blk][i] = v;
                float s1 = v, s2 = v*v;
                for (int o=16;o;o>>=1){
                    s1 += __shfl_xor_sync(0xffffffffu, s1, o);
                    s2 += __shfl_xor_sync(0xffffffffu, s2, o);
                }
                if ((tid & 31) == 0){
                    s_sp[n*4 + sub] = s1;
                    s_sq[n*4 + sub] = s2;
                }
            }
        }
    }
    __syncthreads();

    // ---- gate LN stats finalize ----
    if (tid < 64){
        int n = tid;
        float s1 = s_sp[n*4] + s_sp[n*4+1] + s_sp[n*4+2] + s_sp[n*4+3];
        float s2 = s_sq[n*4] + s_sq[n*4+1] + s_sq[n*4+2] + s_sq[n*4+3];
        float m = s1*(1.f/128.f);
        float var = s2*(1.f/128.f) - m*m;
        s_m[n] = m;
        s_rs[n] = rsqrtf(var + 1e-5f);
    }
    __syncthreads();

    // ---- sigmoid (regs) + upd into s_node ----
    {
        int c = tid & 127, g = tid >> 7;
        float gj = gl_g[c], bj = gl_b[c];
        float hcol[16], vcol[16];
        #pragma unroll
        for (int e=0;e<16;e++){ hcol[e] = s_H[e*132+c]; vcol[e] = s_V[e*132+c]; }
        #pragma unroll
        for (int blk = 0; blk < 4; blk++){
            #pragma unroll
            for (int i=0;i<8;i++){
                int n = g*32 + blk*8 + i;
                float gt = 1.f/(1.f + expf(-((gp[blk][i]-s_m[n])*s_rs[n]*gj + bj)));
                float intra = 0.f, cross = 0.f;
                #pragma unroll
                for (int kk=0; kk<4; kk++){
                    float4 a = ((const float4*)(s_sc  + n*16))[kk];
                    float4 t = ((const float4*)(s_att + n*16))[kk];
                    intra += a.x*hcol[kk*4] + a.y*hcol[kk*4+1] + a.z*hcol[kk*4+2] + a.w*hcol[kk*4+3];
                    cross += t.x*vcol[kk*4] + t.y*vcol[kk*4+1] + t.z*vcol[kk*4+2] + t.w*vcol[kk*4+3];
                }
                s_node[n*132+c] = s_node[n*132+c] + gt*intra + (1.f-gt)*cross;
            }
        }
    }
    __syncthreads();

    // ---- nproj via bf16 tensor cores; weights streamed from global ----
    {
        int lane = tid & 31, w = tid >> 5;     // 8 warps
        int nb  = (w & 3) * 16;
        int jb0 = (w >> 2) * 64;
        int g = lane >> 2, t = lane & 3;
        const float* An0 = s_node + (nb + g)*132;
        const float* An1 = s_node + (nb + g + 8)*132;

        float acc[8][4];
        #pragma unroll
        for (int jt=0;jt<8;jt++){
            acc[jt][0]=0.f; acc[jt][1]=0.f; acc[jt][2]=0.f; acc[jt][3]=0.f;
        }

        #pragma unroll 2
        for (int kc = 0; kc < 8; kc++){
            int kb = kc*16;
            float2 p0 = *(const float2*)(An0 + kb + 2*t);
            float2 p1 = *(const float2*)(An1 + kb + 2*t);
            float2 p2 = *(const float2*)(An0 + kb + 2*t + 8);
            float2 p3 = *(const float2*)(An1 + kb + 2*t + 8);
            unsigned int aH[4], aL[4];
            bf16_split2(p0, aH[0], aL[0]);
            bf16_split2(p1, aH[1], aL[1]);
            bf16_split2(p2, aH[2], aL[2]);
            bf16_split2(p3, aH[3], aL[3]);
            #pragma unroll
            for (int jt = 0; jt < 8; jt++){
                int j = jb0 + jt*8 + g;
                uint2 w0 = __ldg(&g_whl[j*64 + kc*8 + t]);
                uint2 w1 = __ldg(&g_whl[j*64 + kc*8 + t + 4]);
                mma_bf16(acc[jt], aH, w0.x, w1.x);
                mma_bf16(acc[jt], aH, w0.y, w1.y);
                mma_bf16(acc[jt], aL, w0.x, w1.x);
            }
        }

        int nlo = n0 + nb + g;
        int nhi = nlo + 8;
        #pragma unroll
        for (int jt = 0; jt < 8; jt++){
            int j0 = jb0 + jt*8 + 2*t;
            float bias0 = nproj_b[j0], bias1 = nproj_b[j0+1];
            out[(size_t)(b*CC + j0    )*NN + nlo] = gelu_exact(acc[jt][0] + bias0);
            out[(size_t)(b*CC + j0 + 1)*NN + nlo] = gelu_exact(acc[jt][1] + bias1);
            out[(size_t)(b*CC + j0    )*NN + nhi] = gelu_exact(acc[jt][2] + bias0);
            out[(size_t)(b*CC + j0 + 1)*NN + nhi] = gelu_exact(acc[jt][3] + bias1);
        }
    }
}

// ---------------- launch ----------------
extern "C" void kernel_launch(void* const* d_in, const int* in_sizes, int n_in,
                              void* d_out, int out_size)
{
    const float* fm        = (const float*)d_in[0];
    const float* sc        = (const float*)d_in[1];
    const float* np_g      = (const float*)d_in[2];
    const float* np_b      = (const float*)d_in[3];
    const float* mha_w_in  = (const float*)d_in[4];
    const float* mha_b_in  = (const float*)d_in[5];
    const float* mha_w_out = (const float*)d_in[6];
    const float* mha_b_out = (const float*)d_in[7];
    const float* ffn_w1    = (const float*)d_in[8];
    const float* ffn_b1    = (const float*)d_in[9];
    const float* ffn_w2    = (const float*)d_in[10];
    const float* ffn_b2    = (const float*)d_in[11];
    const float* tnorm_g   = (const float*)d_in[12];
    const float* tnorm_b   = (const float*)d_in[13];
    const float* nh_g      = (const float*)d_in[14];
    const float* nh_b      = (const float*)d_in[15];
    const float* hp_w      = (const float*)d_in[16];
    const float* hp_b      = (const float*)d_in[17];
    const float* q_w       = (const float*)d_in[18];
    const float* q_b       = (const float*)d_in[19];
    const float* kv_w      = (const float*)d_in[20];
    const float* kv_b      = (const float*)d_in[21];
    const float* nf_g      = (const float*)d_in[22];
    const float* nf_b      = (const float*)d_in[23];
    const float* gate_w    = (const float*)d_in[24];
    const float* gate_b    = (const float*)d_in[25];
    const float* gl_g      = (const float*)d_in[26];
    const float* gl_b      = (const float*)d_in[27];
    const float* nproj_w   = (const float*)d_in[28];
    const float* nproj_b   = (const float*)d_in[29];

    const int smem_nodeln = (16512 + 2048 + 8192 + 256) * 4;       // 108032
    const int smem_hyper  = (2112*4 + 4224 + 1024 + 33792) * 4;    // 189952
    const int smem_node   = (8448 + 2112*5 + 1024*2 + 256*2
                             + 128*2 + 64*2 + 256*2 + 48) * 4;     // 90048

    cudaFuncSetAttribute(k_node_ln, cudaFuncAttributeMaxDynamicSharedMemorySize, smem_nodeln);
    cudaFuncSetAttribute(k_hyper,   cudaFuncAttributeMaxDynamicSharedMemorySize, smem_hyper);
    cudaFuncSetAttribute(k_node,    cudaFuncAttributeMaxDynamicSharedMemorySize, smem_node);

    k_node_ln<<<576, 512, smem_nodeln>>>(fm, np_g, np_b, sc);
    k_reduce_prep<<<52, 512>>>(gate_w, gate_b, nf_g, nf_b, nproj_w);
    k_hyper<<<8, 1024, smem_hyper>>>(mha_w_in, mha_b_in, mha_w_out, mha_b_out,
                                     ffn_w1, ffn_b1, ffn_w2, ffn_b2,
                                     tnorm_g, tnorm_b, nh_g, nh_b,
                                     hp_w, hp_b, kv_w, kv_b,
                                     q_w, q_b, gate_w, nf_g);
    k_node<<<1152, 256, smem_node>>>(sc, gl_g, gl_b, nproj_b, (float*)d_out);
}

// round 16
// speedup vs baseline: 1.0968x; 1.0968x over previous
#include <cuda_runtime.h>
#include <cuda_bf16.h>
#include <math.h>

#define BB 8
#define CC 128
#define NN 9216
#define EE 16

// ---------------- scratch ----------------
__device__ float g_node [BB*NN*CC];
__device__ float g_part [BB*72*EE*CC];
__device__ float g_hyper [BB*EE*CC];
__device__ float g_hyperF[BB*EE*CC];
__device__ float g_K [BB*EE*CC];
__device__ float g_V [BB*EE*CC];
__device__ float g_Kp[BB*EE*CC];
__device__ float g_kb[BB*EE];
__device__ float g_Hw[BB*EE*CC];
__device__ float g_Vw[BB*EE*CC];
__device__ float g_GH[BB*EE*EE];
__device__ float g_GV[BB*EE*EE];
__device__ float g_hs[BB*EE];
__device__ float g_vs[BB*EE];
__device__ float g_u[CC];
__device__ float g_t[CC];
__device__ uint2 g_wp[CC*64];   // nproj_w bf16 (hi,lo), warp-coalesced packing

__device__ __forceinline__ float gelu_exact(float x){
    return 0.5f*x*(1.0f + erff(x*0.70710678118654752f));
}

__device__ __forceinline__ void mma_bf16(float* d, const unsigned int* a,
                                         unsigned int b0, unsigned int b1){
    asm volatile(
      "mma.sync.aligned.m16n8k16.row.col.f32.bf16.bf16.f32 "
      "{%0,%1,%2,%3}, {%4,%5,%6,%7}, {%8,%9}, {%0,%1,%2,%3};\n"
      : "+f"(d[0]), "+f"(d[1]), "+f"(d[2]), "+f"(d[3])
      : "r"(a[0]), "r"(a[1]), "r"(a[2]), "r"(a[3]), "r"(b0), "r"(b1));
}

__device__ __forceinline__ void bf16_split2(float2 v, unsigned int& hi, unsigned int& lo){
    __nv_bfloat162 h = __float22bfloat162_rn(v);
    float2 back = __bfloat1622float2(h);
    __nv_bfloat162 l = __float22bfloat162_rn(make_float2(v.x - back.x, v.y - back.y));
    hi = *(unsigned int*)&h;
    lo = *(unsigned int*)&l;
}

// ============ kernel 1: transpose + LayerNorm(node) + agg partials ============
__global__ void __launch_bounds__(512)
k_node_ln(const float* __restrict__ fm,
          const float* __restrict__ gam,
          const float* __restrict__ bet,
          const float* __restrict__ sc)
{
    extern __shared__ float sm[];
    float* tile   = sm;              // 128*129
    float* s_sc   = tile + 16512;    // 2048
    float* s_part = s_sc + 2048;     // 8192
    float* s_mean = s_part + 8192;   // 128
    float* s_rstd = s_mean + 128;    // 128
    int b  = blockIdx.x / 72;
    int n0 = (blockIdx.x % 72) * 128;
    int tid = threadIdx.x;

    for (int i = tid; i < 16384; i += 512){
        int c = i >> 7, n = i & 127;
        tile[n*129 + c] = fm[(size_t)(b*CC + c)*NN + n0 + n];
    }
    for (int i = tid; i < 2048; i += 512)
        s_sc[i] = sc[(size_t)(b*NN + n0)*EE + i];
    __syncthreads();

    int w = tid >> 5, lane = tid & 31;
    for (int n = w*8; n < w*8 + 8; n++){
        float v0 = tile[n*129+lane],    v1 = tile[n*129+lane+32];
        float v2 = tile[n*129+lane+64], v3 = tile[n*129+lane+96];
        float s = v0+v1+v2+v3;
        for (int o=16;o;o>>=1) s += __shfl_xor_sync(0xffffffffu, s, o);
        float m = s * (1.0f/128.0f);
        float d0=v0-m, d1=v1-m, d2=v2-m, d3=v3-m;
        float q = d0*d0+d1*d1+d2*d2+d3*d3;
        for (int o=16;o;o>>=1) q += __shfl_xor_sync(0xffffffffu, q, o);
        if (lane == 0){ s_mean[n]=m; s_rstd[n]=rsqrtf(q*(1.0f/128.0f)+1e-5f); }
    }
    __syncthreads();

    int c = tid & 127, q = tid >> 7;
    float gg = gam[c], bb = bet[c];
    float acc[16];
    #pragma unroll
    for (int e=0;e<16;e++) acc[e]=0.f;
    for (int n = q*32; n < q*32 + 32; n++){
        float v = (tile[n*129+c]-s_mean[n])*s_rstd[n]*gg + bb;
        g_node[(size_t)(b*NN + n0 + n)*CC + c] = v;
        const float4* scr = (const float4*)(s_sc + n*16);
        float4 a0 = scr[0], a1 = scr[1], a2 = scr[2], a3 = scr[3];
        acc[0]  += a0.x*v; acc[1]  += a0.y*v; acc[2]  += a0.z*v; acc[3]  += a0.w*v;
        acc[4]  += a1.x*v; acc[5]  += a1.y*v; acc[6]  += a1.z*v; acc[7]  += a1.w*v;
        acc[8]  += a2.x*v; acc[9]  += a2.y*v; acc[10] += a2.z*v; acc[11] += a2.w*v;
        acc[12] += a3.x*v; acc[13] += a3.y*v; acc[14] += a3.z*v; acc[15] += a3.w*v;
    }
    #pragma unroll
    for (int e=0;e<16;e++) s_part[q*2048 + e*128 + c] = acc[e];
    __syncthreads();

    for (int i = tid; i < 2048; i += 512){
        float s = s_part[i] + s_part[2048+i] + s_part[4096+i] + s_part[6144+i];
        g_part[(size_t)(b*72 + (blockIdx.x%72))*2048 + i] = s;
    }
}

// ============ kernel 2: reduce + batch-independent precomputes ============
__global__ void __launch_bounds__(512)
k_reduce_prep(const float* __restrict__ gate_w, const float* __restrict__ gate_b,
              const float* __restrict__ nf_g, const float* __restrict__ nf_b,
              const float* __restrict__ nproj_w)
{
    int blk = blockIdx.x, tid = threadIdx.x;
    if (blk < 32){
        int i = blk*512 + tid;
        int b = i >> 11, rem = i & 2047;
        float s = 0.f;
        #pragma unroll 4
        for (int j = 0; j < 72; j++) s += g_part[(size_t)(b*72 + j)*2048 + rem];
        g_hyper[b*2048 + rem] = s;
    } else if (blk < 36){
        int j = (blk-32)*32 + (tid >> 4);
        int l = tid & 15;
        float t = 0.f, u = 0.f;
        #pragma unroll
        for (int k = 0; k < 16; k++){
            int c = l + k*16;
            float w = gate_w[j*256 + c];
            t += nf_b[c]*w; u += nf_g[c]*w;
        }
        #pragma unroll
        for (int o = 8; o; o >>= 1){
            t += __shfl_xor_sync(0xffffffffu, t, o);
            u += __shfl_xor_sync(0xffffffffu, u, o);
        }
        if (l == 0){ g_t[j] = t + gate_b[j]; g_u[j] = u; }
    } else {
        // warp-coalesced weight packing:
        // g_wp[(((jh*8+jt)*8+kc)*2+h)*32 + g*4+tt]
        //   = split(nproj_w float2[(jh*64 + jt*8 + g)*64 + kc*8 + h*4 + tt])
        int o = (blk-36)*512 + tid;       // 8192 total
        int lane5 = o & 31, grp = o >> 5;
        int h  = grp & 1;
        int kc = (grp >> 1) & 7;
        int jt = (grp >> 4) & 7;
        int jh = grp >> 7;
        int g  = lane5 >> 2, tt = lane5 & 3;
        int src = (jh*64 + jt*8 + g)*64 + kc*8 + h*4 + tt;
        unsigned int hi, lo;
        bf16_split2(((const float2*)nproj_w)[src], hi, lo);
        g_wp[o] = make_uint2(hi, lo);
    }
}

// ============ kernel 3: hyperedge transformer (1024 threads) ============
template<int CIN, int COUT, int ACT, int BS>
__device__ __forceinline__ void gemmF(const float* __restrict__ W,
                                      const float* __restrict__ bias,
                                      const float* in, int inPitch,
                                      float* out, int outPitch, float* sw)
{
    const int pitch = CIN + 4;
    const int cin4  = CIN >> 2;
    const float4* W4 = (const float4*)W;
    for (int i = threadIdx.x; i < (COUT*CIN)>>2; i += BS){
        int r = i / cin4, c4 = i - r*cin4;
        ((float4*)(sw + r*pitch))[c4] = W4[i];
    }
    __syncthreads();
    const int logC  = (COUT == 256) ? 8 : 7;
    const int estep = BS >> logC;
    const int nE    = 16 / estep;
    int j  = threadIdx.x & (COUT-1);
    int e0 = threadIdx.x >> logC;
    const float4* wr = (const float4*)(sw + j*pitch);
    float acc[nE];
    const float4* ar[nE];
    #pragma unroll
    for (int r=0;r<nE;r++){ acc[r]=0.f; ar[r]=(const float4*)(in + (e0 + r*estep)*inPitch); }
    for (int kk = 0; kk < cin4; kk++){
        float4 wv = wr[kk];
        #pragma unroll
        for (int r=0;r<nE;r++){
            float4 av = ar[r][kk];
            acc[r] += av.x*wv.x + av.y*wv.y + av.z*wv.z + av.w*wv.w;
        }
    }
    float bj = bias[j];
    #pragma unroll
    for (int r=0;r<nE;r++){
        float v = acc[r] + bj;
        if (ACT) v = gelu_exact(v);
        out[(e0 + r*estep)*outPitch + j] = v;
    }
    __syncthreads();
}

__device__ __forceinline__ void ln16_128(const float* a, const float* r, int pitch,
                                         const float* __restrict__ g,
                                         const float* __restrict__ b,
                                         float* out, int outPitch)
{
    int w = threadIdx.x >> 5, lane = threadIdx.x & 31;
    if (w < 16){
        float v[4]; float s = 0.f;
        #pragma unroll
        for (int i=0;i<4;i++){
            float x = a[w*pitch + lane + 32*i];
            if (r) x += r[w*pitch + lane + 32*i];
            v[i] = x; s += x;
        }
        for (int o=16;o;o>>=1) s += __shfl_xor_sync(0xffffffffu, s, o);
        float m = s*(1.f/128.f), q = 0.f;
        #pragma unroll
        for (int i=0;i<4;i++){ float d=v[i]-m; q += d*d; }
        for (int o=16;o;o>>=1) q += __shfl_xor_sync(0xffffffffu, q, o);
        float rs = rsqrtf(q*(1.f/128.f)+1e-5f);
        #pragma unroll
        for (int i=0;i<4;i++)
            out[w*outPitch + lane + 32*i] = (v[i]-m)*rs*g[lane+32*i] + b[lane+32*i];
    }
    __syncthreads();
}

__global__ void __launch_bounds__(1024)
k_hyper(const float* __restrict__ mha_w_in, const float* __restrict__ mha_b_in,
        const float* __restrict__ mha_w_out, const float* __restrict__ mha_b_out,
        const float* __restrict__ ffn_w1, const float* __restrict__ ffn_b1,
        const float* __restrict__ ffn_w2, const float* __restrict__ ffn_b2,
        const float* __restrict__ tnorm_g, const float* __restrict__ tnorm_b,
        const float* __restrict__ nh_g, const float* __restrict__ nh_b,
        const float* __restrict__ hp_w, const float* __restrict__ hp_b,
        const float* __restrict__ kv_w, const float* __restrict__ kv_b)
{
    extern __shared__ float sm[];
    float* s0   = sm;            // 16*132
    float* s1   = s0 + 2112;
    float* s2   = s1 + 2112;
    float* s3   = s2 + 2112;
    float* sh   = s3 + 2112;     // 16*264
    float* satt = sh + 4224;     // 1024
    float* sw   = satt + 1024;   // 33792
    int b = blockIdx.x, tid = threadIdx.x;

    for (int i = tid; i < 2048; i += 1024)
        s0[(i>>7)*132 + (i&127)] = g_hyper[b*2048 + i];
    __syncthreads();

    gemmF<128,128,0,1024>(mha_w_in,           mha_b_in,     s0,132, s1,132, sw);
    gemmF<128,128,0,1024>(mha_w_in + 128*128, mha_b_in+128, s0,132, s2,132, sw);
    gemmF<128,128,0,1024>(mha_w_in + 256*128, mha_b_in+256, s0,132, s3,132, sw);

    {
        int p = tid;
        if (p < 1024){
            int h = p>>8, e1 = (p>>4)&15, e2 = p&15;
            const float* qr = s1 + e1*132 + h*32;
            const float* kr = s2 + e2*132 + h*32;
            float acc = 0.f;
            #pragma unroll
            for (int d=0; d<32; d++) acc += qr[d]*kr[d];
            satt[p] = acc * 0.17677669529663687f;
        }
    }
    __syncthreads();
    if (tid < 64){
        float* row = satt + tid*16;
        float mx = row[0];
        #pragma unroll
        for (int e=1;e<16;e++) mx = fmaxf(mx, row[e]);
        float s = 0.f;
        #pragma unroll
        for (int e=0;e<16;e++){ float v = expf(row[e]-mx); row[e]=v; s+=v; }
        float inv = 1.f/s;
        #pragma unroll
        for (int e=0;e<16;e++) row[e] *= inv;
    }
    __syncthreads();
    for (int p = tid; p < 2048; p += 1024){
        int e = p>>7, c = p&127, h = c>>5;
        float acc = 0.f;
        #pragma unroll
        for (int e2=0;e2<16;e2++) acc += satt[(h*16+e)*16 + e2] * s3[e2*132 + c];
        s1[e*132 + c] = acc;
    }
    __syncthreads();
    gemmF<128,128,0,1024>(mha_w_out, mha_b_out, s1,132, s2,132, sw);
    ln16_128(s0, s2, 132, tnorm_g, tnorm_b, s3, 132);
    gemmF<128,256,1,1024>(ffn_w1, ffn_b1, s3,132, sh,264, sw);
    gemmF<256,128,0,1024>(ffn_w2, ffn_b2, sh,264, s1,132, sw);
    ln16_128(s3, s1, 132, tnorm_g, tnorm_b, s2, 132);
    ln16_128(s2, (const float*)0, 132, nh_g, nh_b, s3, 132);
    gemmF<128,128,1,1024>(hp_w, hp_b, s3,132, s0,132, sw);               // H -> s0
    gemmF<128,128,0,1024>(kv_w,           kv_b,     s0,132, s1,132, sw); // K -> s1
    gemmF<128,128,0,1024>(kv_w + 128*128, kv_b+128, s0,132, s2,132, sw); // V -> s2

    for (int i = tid; i < 2048; i += 1024){
        int e = i>>7, c = i&127, o = b*2048 + i;
        g_hyperF[o] = s0[e*132+c];
        g_K[o]      = s1[e*132+c];
        g_V[o]      = s2[e*132+c];
    }
}

// ============ kernel 3b: per-batch precomputes (grid 32) ============
__global__ void __launch_bounds__(512)
k_prep(const float* __restrict__ q_w, const float* __restrict__ q_b,
       const float* __restrict__ gate_w,
       const float* __restrict__ nf_g)
{
    extern __shared__ float sm[];
    float* s_w = sm;            // 128*132
    float* s_a = s_w + 16896;   // 16*132
    float* s_b = s_a + 2112;    // 16*132
    int tid = threadIdx.x;
    int b = blockIdx.x >> 2, task = blockIdx.x & 3;

    if (task == 0){
        for (int i = tid; i < 16384; i += 512){
            int j = i >> 7, k = i & 127;
            s_w[k*132 + j] = q_w[i];
        }
        for (int i4 = tid; i4 < 512; i4 += 512){
            int e = i4 >> 5, c4 = i4 & 31;
            ((float4*)(s_a + e*132))[c4] = ((const float4*)(g_K + b*2048))[i4];
        }
        __syncthreads();
        const float scl = 0.08838834764831845f;
        for (int o = tid; o < 2048; o += 512){
            int e = o>>7, k = o&127;
            const float4* ar = (const float4*)(s_a + e*132);
            const float4* wr = (const float4*)(s_w + k*132);
            float acc = 0.f;
            #pragma unroll 8
            for (int kk = 0; kk < 32; kk++){
                float4 a = ar[kk], w = wr[kk];
                acc += a.x*w.x + a.y*w.y + a.z*w.z + a.w*w.w;
            }
            g_Kp[b*2048 + o] = acc * scl;
        }
        if (tid < 16){
            float acc = 0.f;
            for (int c = 0; c < 128; c++) acc += q_b[c]*s_a[tid*132+c];
            g_kb[b*16 + tid] = acc * scl;
        }
    } else if (task == 1 || task == 2){
        int off = (task == 2) ? 128 : 0;
        const float* src = (task == 2) ? (g_V + b*2048) : (g_hyperF + b*2048);
        for (int i = tid; i < 16384; i += 512){
            int j = i >> 7, c = i & 127;
            s_w[j*132 + c] = gate_w[j*256 + off + c] * nf_g[off + c];
        }
        for (int i4 = tid; i4 < 512; i4 += 512){
            int e = i4 >> 5, c4 = i4 & 31;
            ((float4*)(s_a + e*132))[c4] = ((const float4*)src)[i4];
        }
        __syncthreads();
        float* dst = (task == 2) ? (g_Vw + b*2048) : (g_Hw + b*2048);
        for (int p = tid; p < 2048; p += 512){
            int e = p >> 7, j = p & 127;
            const float4* ar = (const float4*)(s_a + e*132);
            const float4* wr = (const float4*)(s_w + j*132);
            float acc = 0.f;
            #pragma unroll 8
            for (int kk = 0; kk < 32; kk++){
                float4 a = ar[kk], w = wr[kk];
                acc += a.x*w.x + a.y*w.y + a.z*w.z + a.w*w.w;
            }
            dst[p] = acc;
        }
    } else {
        for (int i4 = tid; i4 < 1024; i4 += 512){
            int half = i4 >> 9, q = i4 & 511;
            int e = q >> 5, c4 = q & 31;
            float* dst = half ? s_b : s_a;
            const float4* src = half ? (const float4*)(g_V + b*2048)
                                     : (const float4*)(g_hyperF + b*2048);
            ((float4*)(dst + e*132))[c4] = src[q];
        }
        __syncthreads();
        if (tid < 512){
            const float* A = (tid < 256) ? s_a : s_b;
            int qq = tid & 255;
            int e = qq >> 4, f = qq & 15;
            const float4* r1 = (const float4*)(A + e*132);
            const float4* r2 = (const float4*)(A + f*132);
            float acc = 0.f;
            #pragma unroll 8
            for (int kk = 0; kk < 32; kk++){
                float4 a = r1[kk], c = r2[kk];
                acc += a.x*c.x + a.y*c.y + a.z*c.z + a.w*c.w;
            }
            if (tid < 256) g_GH[b*256+qq] = acc; else g_GV[b*256+qq] = acc;
        }
        if (tid < 32){
            int e = tid & 15;
            const float* A = (tid < 16) ? s_a : s_b;
            float s = 0.f;
            for (int c = 0; c < 128; c++) s += A[e*132+c];
            if (tid < 16) g_hs[b*16+e] = s; else g_vs[b*16+e] = s;
        }
    }
}

// ============ kernel 4: FUSED per-node pipeline ============
// grid 1152 (8*144), block 256, 64 nodes/block, ~90KB smem -> 2 blocks/SM
__global__ void __launch_bounds__(256)
k_node(const float* __restrict__ sc,
       const float* __restrict__ gl_g, const float* __restrict__ gl_b,
       const float* __restrict__ nproj_b,
       float* __restrict__ out)
{
    extern __shared__ float sm[];
    float* s_node = sm;              // 8448 (64*132)
    float* s_Kp   = s_node + 8448;   // 2112
    float* s_H    = s_Kp   + 2112;
    float* s_V    = s_H    + 2112;
    float* s_Hw   = s_V    + 2112;
    float* s_Vw   = s_Hw   + 2112;
    float* s_att  = s_Vw   + 2112;   // 1024 (64*16)
    float* s_sc   = s_att  + 1024;   // 1024
    float* s_GH   = s_sc   + 1024;   // 256
    float* s_GV   = s_GH   + 256;
    float* s_u    = s_GV   + 256;    // 128
    float* s_t    = s_u    + 128;
    float* s_m    = s_t    + 128;    // 64
    float* s_rs   = s_m    + 64;
    float* s_sp   = s_rs   + 64;     // 256 (64*4)
    float* s_sq   = s_sp   + 256;    // 256
    float* s_hs   = s_sq   + 256;    // 16
    float* s_vs   = s_hs   + 16;
    float* s_kb   = s_vs   + 16;

    int b  = blockIdx.x / 144;
    int n0 = (blockIdx.x % 144) * 64;
    int tid = threadIdx.x;

    // ---- stage ----
    for (int i4 = tid; i4 < 2048; i4 += 256){
        int n = i4 >> 5, c4 = i4 & 31;
        ((float4*)(s_node + n*132))[c4] =
            ((const float4*)(g_node + (size_t)(b*NN + n0 + n)*CC))[c4];
    }
    for (int i4 = tid; i4 < 512; i4 += 256){
        int e = i4 >> 5, c4 = i4 & 31;
        ((float4*)(s_Kp + e*132))[c4] = ((const float4*)(g_Kp    + b*2048))[i4];
        ((float4*)(s_H  + e*132))[c4] = ((const float4*)(g_hyperF+ b*2048))[i4];
        ((float4*)(s_V  + e*132))[c4] = ((const float4*)(g_V     + b*2048))[i4];
        ((float4*)(s_Hw + e*132))[c4] = ((const float4*)(g_Hw    + b*2048))[i4];
        ((float4*)(s_Vw + e*132))[c4] = ((const float4*)(g_Vw    + b*2048))[i4];
    }
    {
        int i4 = tid;
        if (i4 < 256) ((float4*)s_sc)[i4] = ((const float4*)(sc + (size_t)(b*NN + n0)*16))[i4];
        if (i4 < 64){
            ((float4*)s_GH)[i4] = ((const float4*)(g_GH + b*256))[i4];
            ((float4*)s_GV)[i4] = ((const float4*)(g_GV + b*256))[i4];
        }
        if (i4 < 32){
            ((float4*)s_u)[i4] = ((const float4*)g_u)[i4];
            ((float4*)s_t)[i4] = ((const float4*)g_t)[i4];
        }
        if (i4 < 16){ s_hs[i4]=g_hs[b*16+i4]; s_vs[i4]=g_vs[b*16+i4]; s_kb[i4]=g_kb[b*16+i4]; }
    }
    __syncthreads();

    // ---- logits ----
    {
        int n = tid >> 2, q = tid & 3;
        const float4* nr = (const float4*)(s_node + n*132);
        float acc[4] = {0.f,0.f,0.f,0.f};
        const float4* kp0 = (const float4*)(s_Kp + (q*4+0)*132);
        const float4* kp1 = (const float4*)(s_Kp + (q*4+1)*132);
        const float4* kp2 = (const float4*)(s_Kp + (q*4+2)*132);
        const float4* kp3 = (const float4*)(s_Kp + (q*4+3)*132);
        #pragma unroll 8
        for (int kk = 0; kk < 32; kk++){
            float4 a = nr[kk];
            float4 k0 = kp0[kk], k1 = kp1[kk], k2 = kp2[kk], k3 = kp3[kk];
            acc[0] += a.x*k0.x + a.y*k0.y + a.z*k0.z + a.w*k0.w;
            acc[1] += a.x*k1.x + a.y*k1.y + a.z*k1.z + a.w*k1.w;
            acc[2] += a.x*k2.x + a.y*k2.y + a.z*k2.z + a.w*k2.w;
            acc[3] += a.x*k3.x + a.y*k3.y + a.z*k3.z + a.w*k3.w;
        }
        #pragma unroll
        for (int i=0;i<4;i++) s_att[n*16 + q*4 + i] = acc[i] + s_kb[q*4+i];
    }
    __syncthreads();

    // ---- softmax + LN256 stats (tid<64) ----
    if (tid < 64){
        int n = tid;
        float scv[16], atv[16];
        float* row = s_att + n*16;
        float mx = row[0];
        #pragma unroll
        for (int e=1;e<16;e++) mx = fmaxf(mx, row[e]);
        float s = 0.f;
        #pragma unroll
        for (int e=0;e<16;e++){ float v = expf(row[e]-mx); atv[e]=v; s+=v; }
        float inv = 1.f/s;
        #pragma unroll
        for (int e=0;e<16;e++){ atv[e] *= inv; row[e] = atv[e]; scv[e] = s_sc[n*16+e]; }
        float mean = 0.f;
        #pragma unroll
        for (int e=0;e<16;e++) mean += scv[e]*s_hs[e] + atv[e]*s_vs[e];
        mean *= (1.f/256.f);
        float ssq = 0.f;
        #pragma unroll
        for (int e=0;e<16;e++){
            float t1 = 0.f, t2 = 0.f;
            #pragma unroll
            for (int f=0;f<16;f++){
                t1 += scv[f]*s_GH[e*16+f];
                t2 += atv[f]*s_GV[e*16+f];
            }
            ssq += scv[e]*t1 + atv[e]*t2;
        }
        float var = ssq*(1.f/256.f) - mean*mean;
        s_m[n] = mean;
        s_rs[n] = rsqrtf(var + 1e-5f);
    }
    __syncthreads();

    // ---- gate rank-16 in registers + LN stat partials ----
    float gp[4][8];
    {
        int j = tid & 127, g = tid >> 7, sub = (tid >> 5) & 3;
        float uj = s_u[j], tj = s_t[j];
        #pragma unroll
        for (int blk = 0; blk < 4; blk++){
            int nb = g*32 + blk*8;
            float acc[8] = {0,0,0,0,0,0,0,0};
            #pragma unroll
            for (int kk = 0; kk < 4; kk++){
                float b0 = s_Hw[(kk*4+0)*132 + j];
                float b1 = s_Hw[(kk*4+1)*132 + j];
                float b2 = s_Hw[(kk*4+2)*132 + j];
                float b3 = s_Hw[(kk*4+3)*132 + j];
                #pragma unroll
                for (int i=0;i<8;i++){
                    float4 a = ((const float4*)(s_sc + (nb+i)*16))[kk];
                    acc[i] += a.x*b0 + a.y*b1 + a.z*b2 + a.w*b3;
                }
            }
            #pragma unroll
            for (int kk = 0; kk < 4; kk++){
                float b0 = s_Vw[(kk*4+0)*132 + j];
                float b1 = s_Vw[(kk*4+1)*132 + j];
                float b2 = s_Vw[(kk*4+2)*132 + j];
                float b3 = s_Vw[(kk*4+3)*132 + j];
                #pragma unroll
                for (int i=0;i<8;i++){
                    float4 a = ((const float4*)(s_att + (nb+i)*16))[kk];
                    acc[i] += a.x*b0 + a.y*b1 + a.z*b2 + a.w*b3;
                }
            }
            #pragma unroll
            for (int i=0;i<8;i++){
                int n = nb + i;
                float v = s_rs[n]*(acc[i] - s_m[n]*uj) + tj;
                gp[blk][i] = v;
                float s1 = v, s2 = v*v;
                for (int o=16;o;o>>=1){
                    s1 += __shfl_xor_sync(0xffffffffu, s1, o);
                    s2 += __shfl_xor_sync(0xffffffffu, s2, o);
                }
                if ((tid & 31) == 0){
                    s_sp[n*4 + sub] = s1;
                    s_sq[n*4 + sub] = s2;
                }
            }
        }
    }
    __syncthreads();

    // ---- gate LN stats finalize ----
    if (tid < 64){
        int n = tid;
        float s1 = s_sp[n*4] + s_sp[n*4+1] + s_sp[n*4+2] + s_sp[n*4+3];
        float s2 = s_sq[n*4] + s_sq[n*4+1] + s_sq[n*4+2] + s_sq[n*4+3];
        float m = s1*(1.f/128.f);
        float var = s2*(1.f/128.f) - m*m;
        s_m[n] = m;
        s_rs[n] = rsqrtf(var + 1e-5f);
    }
    __syncthreads();

    // ---- sigmoid (regs) + upd into s_node ----
    {
        int c = tid & 127, g = tid >> 7;
        float gj = gl_g[c], bj = gl_b[c];
        float hcol[16], vcol[16];
        #pragma unroll
        for (int e=0;e<16;e++){ hcol[e] = s_H[e*132+c]; vcol[e] = s_V[e*132+c]; }
        #pragma unroll
        for (int blk = 0; blk < 4; blk++){
            #pragma unroll
            for (int i=0;i<8;i++){
                int n = g*32 + blk*8 + i;
                float gt = 1.f/(1.f + expf(-((gp[blk][i]-s_m[n])*s_rs[n]*gj + bj)));
                float intra = 0.f, cross = 0.f;
                #pragma unroll
                for (int kk=0; kk<4; kk++){
                    float4 a = ((const float4*)(s_sc  + n*16))[kk];
                    float4 t = ((const float4*)(s_att + n*16))[kk];
                    intra += a.x*hcol[kk*4] + a.y*hcol[kk*4+1] + a.z*hcol[kk*4+2] + a.w*hcol[kk*4+3];
                    cross += t.x*vcol[kk*4] + t.y*vcol[kk*4+1] + t.z*vcol[kk*4+2] + t.w*vcol[kk*4+3];
                }
                s_node[n*132+c] = s_node[n*132+c] + gt*intra + (1.f-gt)*cross;
            }
        }
    }
    __syncthreads();

    // ---- nproj via bf16 tensor cores; warp-coalesced weight loads ----
    {
        int lane = tid & 31, w = tid >> 5;     // 8 warps
        int nb  = (w & 3) * 16;
        int jh  = (w >> 2);                    // 0 or 1 (j half)
        int jb0 = jh * 64;
        int g = lane >> 2, t = lane & 3;
        const float* An0 = s_node + (nb + g)*132;
        const float* An1 = s_node + (nb + g + 8)*132;

        float acc[8][4];
        #pragma unroll
        for (int jt=0;jt<8;jt++){
            acc[jt][0]=0.f; acc[jt][1]=0.f; acc[jt][2]=0.f; acc[jt][3]=0.f;
        }

        #pragma unroll 2
        for (int kc = 0; kc < 8; kc++){
            int kb = kc*16;
            float2 p0 = *(const float2*)(An0 + kb + 2*t);
            float2 p1 = *(const float2*)(An1 + kb + 2*t);
            float2 p2 = *(const float2*)(An0 + kb + 2*t + 8);
            float2 p3 = *(const float2*)(An1 + kb + 2*t + 8);
            unsigned int aH[4], aL[4];
            bf16_split2(p0, aH[0], aL[0]);
            bf16_split2(p1, aH[1], aL[1]);
            bf16_split2(p2, aH[2], aL[2]);
            bf16_split2(p3, aH[3], aL[3]);
            #pragma unroll
            for (int jt = 0; jt < 8; jt++){
                // base = group*64 ; warp loads 32 consecutive uint2 per half
                int base = (((jh*8 + jt)*8 + kc) << 6);
                uint2 w0 = __ldg(&g_wp[base + lane]);        // h=0: g*4+t == lane
                uint2 w1 = __ldg(&g_wp[base + 32 + lane]);   // h=1
                mma_bf16(acc[jt], aH, w0.x, w1.x);
                mma_bf16(acc[jt], aH, w0.y, w1.y);
                mma_bf16(acc[jt], aL, w0.x, w1.x);
            }
        }

        int nlo = n0 + nb + g;
        int nhi = nlo + 8;
        #pragma unroll
        for (int jt = 0; jt < 8; jt++){
            int j0 = jb0 + jt*8 + 2*t;
            float bias0 = nproj_b[j0], bias1 = nproj_b[j0+1];
            out[(size_t)(b*CC + j0    )*NN + nlo] = gelu_exact(acc[jt][0] + bias0);
            out[(size_t)(b*CC + j0 + 1)*NN + nlo] = gelu_exact(acc[jt][1] + bias1);
            out[(size_t)(b*CC + j0    )*NN + nhi] = gelu_exact(acc[jt][2] + bias0);
            out[(size_t)(b*CC + j0 + 1)*NN + nhi] = gelu_exact(acc[jt][3] + bias1);
        }
    }
}

// ---------------- launch ----------------
extern "C" void kernel_launch(void* const* d_in, const int* in_sizes, int n_in,
                              void* d_out, int out_size)
{
    const float* fm        = (const float*)d_in[0];
    const float* sc        = (const float*)d_in[1];
    const float* np_g      = (const float*)d_in[2];
    const float* np_b      = (const float*)d_in[3];
    const float* mha_w_in  = (const float*)d_in[4];
    const float* mha_b_in  = (const float*)d_in[5];
    const float* mha_w_out = (const float*)d_in[6];
    const float* mha_b_out = (const float*)d_in[7];
    const float* ffn_w1    = (const float*)d_in[8];
    const float* ffn_b1    = (const float*)d_in[9];
    const float* ffn_w2    = (const float*)d_in[10];
    const float* ffn_b2    = (const float*)d_in[11];
    const float* tnorm_g   = (const float*)d_in[12];
    const float* tnorm_b   = (const float*)d_in[13];
    const float* nh_g      = (const float*)d_in[14];
    const float* nh_b      = (const float*)d_in[15];
    const float* hp_w      = (const float*)d_in[16];
    const float* hp_b      = (const float*)d_in[17];
    const float* q_w       = (const float*)d_in[18];
    const float* q_b       = (const float*)d_in[19];
    const float* kv_w      = (const float*)d_in[20];
    const float* kv_b      = (const float*)d_in[21];
    const float* nf_g      = (const float*)d_in[22];
    const float* nf_b      = (const float*)d_in[23];
    const float* gate_w    = (const float*)d_in[24];
    const float* gate_b    = (const float*)d_in[25];
    const float* gl_g      = (const float*)d_in[26];
    const float* gl_b      = (const float*)d_in[27];
    const float* nproj_w   = (const float*)d_in[28];
    const float* nproj_b   = (const float*)d_in[29];

    const int smem_nodeln = (16512 + 2048 + 8192 + 256) * 4;       // 108032
    const int smem_hyper  = (2112*4 + 4224 + 1024 + 33792) * 4;    // 189952
    const int smem_prep   = (16896 + 2112*2) * 4;                  // 84480
    const int smem_node   = (8448 + 2112*5 + 1024*2 + 256*2
                             + 128*2 + 64*2 + 256*2 + 48) * 4;     // 90048

    cudaFuncSetAttribute(k_node_ln, cudaFuncAttributeMaxDynamicSharedMemorySize, smem_nodeln);
    cudaFuncSetAttribute(k_hyper,   cudaFuncAttributeMaxDynamicSharedMemorySize, smem_hyper);
    cudaFuncSetAttribute(k_prep,    cudaFuncAttributeMaxDynamicSharedMemorySize, smem_prep);
    cudaFuncSetAttribute(k_node,    cudaFuncAttributeMaxDynamicSharedMemorySize, smem_node);

    k_node_ln<<<576, 512, smem_nodeln>>>(fm, np_g, np_b, sc);
    k_reduce_prep<<<52, 512>>>(gate_w, gate_b, nf_g, nf_b, nproj_w);
    k_hyper<<<8, 1024, smem_hyper>>>(mha_w_in, mha_b_in, mha_w_out, mha_b_out,
                                     ffn_w1, ffn_b1, ffn_w2, ffn_b2,
                                     tnorm_g, tnorm_b, nh_g, nh_b,
                                     hp_w, hp_b, kv_w, kv_b);
    k_prep<<<32, 512, smem_prep>>>(q_w, q_b, gate_w, nf_g);
    k_node<<<1152, 256, smem_node>>>(sc, gl_g, gl_b, nproj_b, (float*)d_out);
}